// round 2
// baseline (speedup 1.0000x reference)
#include <cuda_runtime.h>
#include <cstdint>

#define ALPHA 0.2f
#define BN_EPS 1e-5f
#define MAXN 50176  // padded capacity for N=50000

// ---------------- scratch (device globals; no allocation allowed) ----------------
__device__ float g_z[(size_t)MAXN * 128];     // z = (1+eps)*self + weighted_neigh
__device__ float g_bufA[(size_t)MAXN * 128];
__device__ float g_bufB[(size_t)MAXN * 128];
__device__ float g_Wc[128 * 128];             // W_t @ W1
__device__ float g_wa[128];                   // W_t @ a_neigh
__device__ float g_ws[128];                   // W_t @ a_self
__device__ float g_sum[3 * 128];
__device__ float g_sqs[3 * 128];
__device__ float g_scale[3 * 128];
__device__ float g_shift[3 * 128];

__device__ __forceinline__ float lrelu(float x) { return x > 0.f ? x : ALPHA * x; }

// ---------------- prep: wa, ws, zero stats ----------------
__global__ void prep_kernel(const float* __restrict__ W, const float* __restrict__ a_att) {
    int d = threadIdx.x;  // 0..127
    float wa = 0.f, ws = 0.f;
    #pragma unroll 8
    for (int t = 0; t < 128; ++t) {
        float w = W[d * 128 + t];
        ws += w * a_att[t];
        wa += w * a_att[128 + t];
    }
    g_wa[d] = wa;
    g_ws[d] = ws;
    #pragma unroll
    for (int l = 0; l < 3; ++l) { g_sum[l * 128 + d] = 0.f; g_sqs[l * 128 + d] = 0.f; }
}

// ---------------- Wc = W_t @ W1 (128x128 @ 128x128), 16 blocks x 128 threads ----------------
__global__ void wc_kernel(const float* __restrict__ Wt, const float* __restrict__ W1) {
    __shared__ float s_wt[8][128];
    int r0 = blockIdx.x * 8;
    int c = threadIdx.x;
    #pragma unroll
    for (int i = 0; i < 8; ++i) s_wt[i][c] = Wt[(r0 + i) * 128 + c];
    __syncthreads();
    float acc[8] = {0.f, 0.f, 0.f, 0.f, 0.f, 0.f, 0.f, 0.f};
    #pragma unroll 4
    for (int t = 0; t < 128; ++t) {
        float w1 = W1[t * 128 + c];
        #pragma unroll
        for (int i = 0; i < 8; ++i) acc[i] += s_wt[i][t] * w1;
    }
    #pragma unroll
    for (int i = 0; i < 8; ++i) g_Wc[(r0 + i) * 128 + c] = acc[i];
}

// ---------------- fused attention: scores -> softmax -> weighted sum -> z ----------------
// one block (128 threads / 4 warps) per node n. K <= 28 assumed (K=25).
__global__ __launch_bounds__(128) void attn_kernel(
    const float* __restrict__ self, const float* __restrict__ neigh,
    const float* __restrict__ epsp, int N, int K)
{
    __shared__ float s_raw[32];
    __shared__ float s_attn[32];
    __shared__ float s_sred[4];
    __shared__ float4 s_part[4][32];

    int n = blockIdx.x;
    int tid = threadIdx.x, warp = tid >> 5, lane = tid & 31;

    const float4* nb = (const float4*)neigh + (size_t)n * K * 32;
    const float4* sv = (const float4*)self + (size_t)n * 32;

    float4 wa4 = ((const float4*)g_wa)[lane];

    // self score: s_self = self[n] . ws  (block reduce)
    float sp = self[(size_t)n * 128 + tid] * g_ws[tid];
    #pragma unroll
    for (int off = 16; off; off >>= 1) sp += __shfl_xor_sync(0xffffffffu, sp, off);
    if (lane == 0) s_sred[warp] = sp;

    // load this warp's neighbor rows into registers (k = warp + 4*j)
    float4 v[7];
    #pragma unroll
    for (int j = 0; j < 7; ++j) {
        int k = warp + 4 * j;
        v[j] = (k < K) ? nb[k * 32 + lane] : make_float4(0.f, 0.f, 0.f, 0.f);
    }

    // raw neighbor scores: neigh[n,k] . wa
    #pragma unroll
    for (int j = 0; j < 7; ++j) {
        int k = warp + 4 * j;
        if (k < K) {
            float s = v[j].x * wa4.x + v[j].y * wa4.y + v[j].z * wa4.z + v[j].w * wa4.w;
            #pragma unroll
            for (int off = 16; off; off >>= 1) s += __shfl_xor_sync(0xffffffffu, s, off);
            if (lane == 0) s_raw[k] = s;
        }
    }
    __syncthreads();

    // warp 0: leaky_relu + softmax over K
    if (warp == 0) {
        float ssum = s_sred[0] + s_sred[1] + s_sred[2] + s_sred[3];
        float val = -1e30f;
        if (lane < K) val = lrelu(ssum + s_raw[lane]);
        float m = val;
        #pragma unroll
        for (int off = 16; off; off >>= 1) m = fmaxf(m, __shfl_xor_sync(0xffffffffu, m, off));
        float e = (lane < K) ? expf(val - m) : 0.f;
        float s = e;
        #pragma unroll
        for (int off = 16; off; off >>= 1) s += __shfl_xor_sync(0xffffffffu, s, off);
        s_attn[lane] = e / s;
    }
    __syncthreads();

    // weighted sum over this warp's k's (rows still in registers)
    float4 acc = make_float4(0.f, 0.f, 0.f, 0.f);
    #pragma unroll
    for (int j = 0; j < 7; ++j) {
        int k = warp + 4 * j;
        if (k < K) {
            float a = s_attn[k];
            acc.x += a * v[j].x; acc.y += a * v[j].y;
            acc.z += a * v[j].z; acc.w += a * v[j].w;
        }
    }
    s_part[warp][lane] = acc;
    __syncthreads();

    // warp 0: cross-warp reduce + (1+eps)*self, write z
    if (warp == 0) {
        float4 r0 = s_part[0][lane], r1 = s_part[1][lane];
        float4 r2 = s_part[2][lane], r3 = s_part[3][lane];
        float ce = 1.f + epsp[0];
        float4 sf = sv[lane];
        float4 r;
        r.x = r0.x + r1.x + r2.x + r3.x + ce * sf.x;
        r.y = r0.y + r1.y + r2.y + r3.y + ce * sf.y;
        r.z = r0.z + r1.z + r2.z + r3.z + ce * sf.z;
        r.w = r0.w + r1.w + r2.w + r3.w + ce * sf.w;
        ((float4*)g_z)[(size_t)n * 32 + lane] = r;
    }
}

// ---------------- f32x2-packed GEMM [N,128] @ [128,128] + bias + fused input-BN + column stats
// BM=128 rows/block, full 128 cols, BK=32, 256 threads. Per-thread 8 rows x 8 cols,
// accumulators = 32 packed f32x2 (column pairs). FFMA2 via fma.rn.f32x2.
template <bool IN_BN, bool STATS>
__global__ __launch_bounds__(256, 2) void gemm_f32x2(
    const float* __restrict__ A, const float* __restrict__ W, const float* __restrict__ bias,
    const float* __restrict__ scaleIn, const float* __restrict__ shiftIn,
    float* __restrict__ Y, float* __restrict__ sumOut, float* __restrict__ sqsOut, int N)
{
    __shared__ float As[32 * 132];   // [k][m], padded stride 132
    __shared__ float Ws[32 * 132];   // [k][c], padded stride 132
    __shared__ float red[16 * 128];

    const int tid = threadIdx.x;
    const int tr = tid >> 4;     // 0..15 -> rows tr*8 .. tr*8+7
    const int tc = tid & 15;     // 0..15 -> cols tc*8 .. tc*8+7
    const int rowBase = blockIdx.x * 128;

    const float4* Ag4 = (const float4*)A;
    const float4* Wg4 = (const float4*)W;

    unsigned long long acc[8][4];
    #pragma unroll
    for (int i = 0; i < 8; ++i)
        #pragma unroll
        for (int j = 0; j < 4; ++j) acc[i][j] = 0ull;

    for (int ch = 0; ch < 4; ++ch) {
        // load W chunk: k rows ch*32..+31, all 128 cols (1024 float4, 4 per thread)
        #pragma unroll
        for (int i = 0; i < 4; ++i) {
            int j = tid + i * 256;
            int kk = j >> 5, cq = j & 31;
            float4 w = Wg4[(ch * 32 + kk) * 32 + cq];
            *(float4*)&Ws[kk * 132 + cq * 4] = w;
        }
        // load A chunk: 128 rows x 32 k, transposed into As[k][m] (1024 float4, 4/thread)
        #pragma unroll
        for (int i = 0; i < 4; ++i) {
            int j = tid + i * 256;
            int m = j >> 3, kq = j & 7;
            int grow = rowBase + m;
            float4 a = make_float4(0.f, 0.f, 0.f, 0.f);
            if (grow < N) a = Ag4[(size_t)grow * 32 + ch * 8 + kq];
            if (IN_BN) {
                float4 sc = ((const float4*)scaleIn)[ch * 8 + kq];
                float4 sh = ((const float4*)shiftIn)[ch * 8 + kq];
                a.x = lrelu(sc.x * a.x + sh.x);
                a.y = lrelu(sc.y * a.y + sh.y);
                a.z = lrelu(sc.z * a.z + sh.z);
                a.w = lrelu(sc.w * a.w + sh.w);
            }
            As[(kq * 4 + 0) * 132 + m] = a.x;
            As[(kq * 4 + 1) * 132 + m] = a.y;
            As[(kq * 4 + 2) * 132 + m] = a.z;
            As[(kq * 4 + 3) * 132 + m] = a.w;
        }
        __syncthreads();

        #pragma unroll
        for (int kk = 0; kk < 32; ++kk) {
            float4 a0 = *(const float4*)&As[kk * 132 + tr * 8];
            float4 a1 = *(const float4*)&As[kk * 132 + tr * 8 + 4];
            ulonglong2 b0 = *(const ulonglong2*)&Ws[kk * 132 + tc * 8];
            ulonglong2 b1 = *(const ulonglong2*)&Ws[kk * 132 + tc * 8 + 4];
            unsigned long long bp0 = b0.x, bp1 = b0.y, bp2 = b1.x, bp3 = b1.y;
            float av[8] = {a0.x, a0.y, a0.z, a0.w, a1.x, a1.y, a1.z, a1.w};
            #pragma unroll
            for (int i = 0; i < 8; ++i) {
                unsigned int au = __float_as_uint(av[i]);
                unsigned long long ad;
                asm("mov.b64 %0, {%1, %2};" : "=l"(ad) : "r"(au), "r"(au));
                asm("fma.rn.f32x2 %0, %1, %2, %3;" : "=l"(acc[i][0]) : "l"(ad), "l"(bp0), "l"(acc[i][0]));
                asm("fma.rn.f32x2 %0, %1, %2, %3;" : "=l"(acc[i][1]) : "l"(ad), "l"(bp1), "l"(acc[i][1]));
                asm("fma.rn.f32x2 %0, %1, %2, %3;" : "=l"(acc[i][2]) : "l"(ad), "l"(bp2), "l"(acc[i][2]));
                asm("fma.rn.f32x2 %0, %1, %2, %3;" : "=l"(acc[i][3]) : "l"(ad), "l"(bp3), "l"(acc[i][3]));
            }
        }
        __syncthreads();
    }

    // epilogue: unpack, +bias, store, stats
    float4 bi0 = ((const float4*)bias)[tc * 2];
    float4 bi1 = ((const float4*)bias)[tc * 2 + 1];
    float colSum[8], colSq[8];
    #pragma unroll
    for (int q = 0; q < 8; ++q) { colSum[q] = 0.f; colSq[q] = 0.f; }

    #pragma unroll
    for (int i = 0; i < 8; ++i) {
        int grow = rowBase + tr * 8 + i;
        if (grow < N) {
            float y[8];
            #pragma unroll
            for (int j = 0; j < 4; ++j) {
                unsigned int lo, hi;
                asm("mov.b64 {%0, %1}, %2;" : "=r"(lo), "=r"(hi) : "l"(acc[i][j]));
                y[2 * j]     = __uint_as_float(lo);
                y[2 * j + 1] = __uint_as_float(hi);
            }
            y[0] += bi0.x; y[1] += bi0.y; y[2] += bi0.z; y[3] += bi0.w;
            y[4] += bi1.x; y[5] += bi1.y; y[6] += bi1.z; y[7] += bi1.w;
            float4 o0 = make_float4(y[0], y[1], y[2], y[3]);
            float4 o1 = make_float4(y[4], y[5], y[6], y[7]);
            ((float4*)Y)[(size_t)grow * 32 + tc * 2]     = o0;
            ((float4*)Y)[(size_t)grow * 32 + tc * 2 + 1] = o1;
            if (STATS) {
                #pragma unroll
                for (int q = 0; q < 8; ++q) { colSum[q] += y[q]; colSq[q] += y[q] * y[q]; }
            }
        }
    }

    if (STATS) {
        *(float4*)&red[tr * 128 + tc * 8]     = make_float4(colSum[0], colSum[1], colSum[2], colSum[3]);
        *(float4*)&red[tr * 128 + tc * 8 + 4] = make_float4(colSum[4], colSum[5], colSum[6], colSum[7]);
        __syncthreads();
        if (tid < 128) {
            float t = 0.f;
            #pragma unroll
            for (int r = 0; r < 16; ++r) t += red[r * 128 + tid];
            atomicAdd(&sumOut[tid], t);
        }
        __syncthreads();
        *(float4*)&red[tr * 128 + tc * 8]     = make_float4(colSq[0], colSq[1], colSq[2], colSq[3]);
        *(float4*)&red[tr * 128 + tc * 8 + 4] = make_float4(colSq[4], colSq[5], colSq[6], colSq[7]);
        __syncthreads();
        if (tid < 128) {
            float t = 0.f;
            #pragma unroll
            for (int r = 0; r < 16; ++r) t += red[r * 128 + tid];
            atomicAdd(&sqsOut[tid], t);
        }
    }
}

// ---------------- BN finalize: per-column scale/shift ----------------
__global__ void bn_fin_kernel(const float* __restrict__ sum, const float* __restrict__ sqs,
                              const float* __restrict__ g, const float* __restrict__ be,
                              float* __restrict__ scale, float* __restrict__ shift, float invN)
{
    int c = threadIdx.x;
    float m = sum[c] * invN;
    float var = sqs[c] * invN - m * m;
    float s = g[c] * rsqrtf(var + BN_EPS);
    scale[c] = s;
    shift[c] = be[c] - m * s;
}

// ---------------- final BN + leaky_relu apply ----------------
__global__ void apply_kernel(const float* __restrict__ Y,
                             const float* __restrict__ scale, const float* __restrict__ shift,
                             float* __restrict__ out, int N)
{
    size_t i = (size_t)blockIdx.x * blockDim.x + threadIdx.x;  // float4 index
    if (i < (size_t)N * 32) {
        int c = (int)(i & 31);
        float4 sc = ((const float4*)scale)[c];
        float4 sh = ((const float4*)shift)[c];
        float4 y = ((const float4*)Y)[i];
        float4 o;
        o.x = lrelu(sc.x * y.x + sh.x);
        o.y = lrelu(sc.y * y.y + sh.y);
        o.z = lrelu(sc.z * y.z + sh.z);
        o.w = lrelu(sc.w * y.w + sh.w);
        ((float4*)out)[i] = o;
    }
}

// ---------------- launch ----------------
extern "C" void kernel_launch(void* const* d_in, const int* in_sizes, int n_in,
                              void* d_out, int out_size) {
    const float* self  = (const float*)d_in[0];
    const float* neigh = (const float*)d_in[1];
    const float* W_t   = (const float*)d_in[2];
    const float* a_att = (const float*)d_in[3];
    const float* epsp  = (const float*)d_in[4];
    const float* W1 = (const float*)d_in[5];
    const float* b1 = (const float*)d_in[6];
    const float* g1 = (const float*)d_in[7];
    const float* be1 = (const float*)d_in[8];
    const float* W2 = (const float*)d_in[9];
    const float* b2 = (const float*)d_in[10];
    const float* g2 = (const float*)d_in[11];
    const float* be2 = (const float*)d_in[12];
    const float* W3 = (const float*)d_in[13];
    const float* b3 = (const float*)d_in[14];
    const float* g3 = (const float*)d_in[15];
    const float* be3 = (const float*)d_in[16];

    int N = in_sizes[0] / 128;
    int K = (int)((long long)in_sizes[1] / ((long long)N * 128));

    float *z, *bufA, *bufB, *Wc, *sum, *sqs, *scale, *shift;
    cudaGetSymbolAddress((void**)&z,     g_z);
    cudaGetSymbolAddress((void**)&bufA,  g_bufA);
    cudaGetSymbolAddress((void**)&bufB,  g_bufB);
    cudaGetSymbolAddress((void**)&Wc,    g_Wc);
    cudaGetSymbolAddress((void**)&sum,   g_sum);
    cudaGetSymbolAddress((void**)&sqs,   g_sqs);
    cudaGetSymbolAddress((void**)&scale, g_scale);
    cudaGetSymbolAddress((void**)&shift, g_shift);

    float invN = 1.f / (float)N;
    int gemmGrid = (N + 127) / 128;

    prep_kernel<<<1, 128>>>(W_t, a_att);
    wc_kernel<<<16, 128>>>(W_t, W1);
    attn_kernel<<<N, 128>>>(self, neigh, epsp, N, K);

    // y1 = z @ (W_t@W1) + b1, stats layer 0   (bufA)
    gemm_f32x2<false, true><<<gemmGrid, 256>>>(
        z, Wc, b1, nullptr, nullptr, bufA, sum, sqs, N);
    bn_fin_kernel<<<1, 128>>>(sum, sqs, g1, be1, scale, shift, invN);

    // y2 = act1(y1) @ W2 + b2, stats layer 1  (bufB)
    gemm_f32x2<true, true><<<gemmGrid, 256>>>(
        bufA, W2, b2, scale, shift, bufB, sum + 128, sqs + 128, N);
    bn_fin_kernel<<<1, 128>>>(sum + 128, sqs + 128, g2, be2, scale + 128, shift + 128, invN);

    // y3 = act2(y2) @ W3 + b3, stats layer 2  (bufA)
    gemm_f32x2<true, true><<<gemmGrid, 256>>>(
        bufB, W3, b3, scale + 128, shift + 128, bufA, sum + 256, sqs + 256, N);
    bn_fin_kernel<<<1, 128>>>(sum + 256, sqs + 256, g3, be3, scale + 256, shift + 256, invN);

    // out = act3(y3)
    int applyGrid = (int)(((size_t)N * 32 + 255) / 256);
    apply_kernel<<<applyGrid, 256>>>(bufA, scale + 256, shift + 256, (float*)d_out, N);
}

// round 4
// speedup vs baseline: 1.4336x; 1.4336x over previous
#include <cuda_runtime.h>
#include <cstdint>

#define ALPHA 0.2f
#define BN_EPS 1e-5f
#define MAXN 50176

// ---------------- scratch (device globals) ----------------
__device__ float g_z[(size_t)MAXN * 128];
__device__ float g_bufA[(size_t)MAXN * 128];
__device__ float g_bufB[(size_t)MAXN * 128];
__device__ float g_Wc[128 * 128];             // W_t @ W1
__device__ float g_Bt[3][128 * 128];          // pre-transposed [n][k] tf32 weights
__device__ float g_wa[128];
__device__ float g_ws[128];
__device__ float g_sum[3 * 128];
__device__ float g_sqs[3 * 128];
__device__ float g_scale[3 * 128];
__device__ float g_shift[3 * 128];

__device__ __forceinline__ float lrelu(float x) { return x > 0.f ? x : ALPHA * x; }

__device__ __forceinline__ uint32_t to_tf32(float x) {
    uint32_t r;
    asm("cvt.rna.tf32.f32 %0, %1;" : "=r"(r) : "f"(x));
    return r;
}

// ---------------- prep: wa, ws, zero stats ----------------
__global__ void prep_kernel(const float* __restrict__ W, const float* __restrict__ a_att) {
    int d = threadIdx.x;
    float wa = 0.f, ws = 0.f;
    #pragma unroll 8
    for (int t = 0; t < 128; ++t) {
        float w = W[d * 128 + t];
        ws += w * a_att[t];
        wa += w * a_att[128 + t];
    }
    g_wa[d] = wa;
    g_ws[d] = ws;
    #pragma unroll
    for (int l = 0; l < 3; ++l) { g_sum[l * 128 + d] = 0.f; g_sqs[l * 128 + d] = 0.f; }
}

// ---------------- Wc = W_t @ W1 ----------------
__global__ void wc_kernel(const float* __restrict__ Wt, const float* __restrict__ W1) {
    __shared__ float s_wt[8][128];
    int r0 = blockIdx.x * 8;
    int c = threadIdx.x;
    #pragma unroll
    for (int i = 0; i < 8; ++i) s_wt[i][c] = Wt[(r0 + i) * 128 + c];
    __syncthreads();
    float acc[8] = {0.f, 0.f, 0.f, 0.f, 0.f, 0.f, 0.f, 0.f};
    #pragma unroll 4
    for (int t = 0; t < 128; ++t) {
        float w1 = W1[t * 128 + c];
        #pragma unroll
        for (int i = 0; i < 8; ++i) acc[i] += s_wt[i][t] * w1;
    }
    #pragma unroll
    for (int i = 0; i < 8; ++i) g_Wc[(r0 + i) * 128 + c] = acc[i];
}

// ---------------- buildB: W[k][n] -> Bt[n][k], tf32-rounded ----------------
__global__ void buildB_kernel(const float* __restrict__ src, float* __restrict__ dst) {
    int idx = blockIdx.x * 256 + threadIdx.x;   // 0..16383
    int k = idx >> 7, n = idx & 127;
    uint32_t v = to_tf32(src[k * 128 + n]);
    dst[n * 128 + k] = __uint_as_float(v);
}

// ---------------- fused attention ----------------
__global__ __launch_bounds__(128) void attn_kernel(
    const float* __restrict__ self, const float* __restrict__ neigh,
    const float* __restrict__ epsp, int N, int K)
{
    __shared__ float s_raw[32];
    __shared__ float s_attn[32];
    __shared__ float s_sred[4];
    __shared__ float4 s_part[4][32];

    int n = blockIdx.x;
    int tid = threadIdx.x, warp = tid >> 5, lane = tid & 31;

    const float4* nb = (const float4*)neigh + (size_t)n * K * 32;
    const float4* sv = (const float4*)self + (size_t)n * 32;

    float4 wa4 = ((const float4*)g_wa)[lane];

    float sp = self[(size_t)n * 128 + tid] * g_ws[tid];
    #pragma unroll
    for (int off = 16; off; off >>= 1) sp += __shfl_xor_sync(0xffffffffu, sp, off);
    if (lane == 0) s_sred[warp] = sp;

    float4 v[7];
    #pragma unroll
    for (int j = 0; j < 7; ++j) {
        int k = warp + 4 * j;
        v[j] = (k < K) ? nb[k * 32 + lane] : make_float4(0.f, 0.f, 0.f, 0.f);
    }

    #pragma unroll
    for (int j = 0; j < 7; ++j) {
        int k = warp + 4 * j;
        if (k < K) {
            float s = v[j].x * wa4.x + v[j].y * wa4.y + v[j].z * wa4.z + v[j].w * wa4.w;
            #pragma unroll
            for (int off = 16; off; off >>= 1) s += __shfl_xor_sync(0xffffffffu, s, off);
            if (lane == 0) s_raw[k] = s;
        }
    }
    __syncthreads();

    if (warp == 0) {
        float ssum = s_sred[0] + s_sred[1] + s_sred[2] + s_sred[3];
        float val = -1e30f;
        if (lane < K) val = lrelu(ssum + s_raw[lane]);
        float m = val;
        #pragma unroll
        for (int off = 16; off; off >>= 1) m = fmaxf(m, __shfl_xor_sync(0xffffffffu, m, off));
        float e = (lane < K) ? expf(val - m) : 0.f;
        float s = e;
        #pragma unroll
        for (int off = 16; off; off >>= 1) s += __shfl_xor_sync(0xffffffffu, s, off);
        s_attn[lane] = e / s;
    }
    __syncthreads();

    float4 acc = make_float4(0.f, 0.f, 0.f, 0.f);
    #pragma unroll
    for (int j = 0; j < 7; ++j) {
        int k = warp + 4 * j;
        if (k < K) {
            float a = s_attn[k];
            acc.x += a * v[j].x; acc.y += a * v[j].y;
            acc.z += a * v[j].z; acc.w += a * v[j].w;
        }
    }
    s_part[warp][lane] = acc;
    __syncthreads();

    if (warp == 0) {
        float4 r0 = s_part[0][lane], r1 = s_part[1][lane];
        float4 r2 = s_part[2][lane], r3 = s_part[3][lane];
        float ce = 1.f + epsp[0];
        float4 sf = sv[lane];
        float4 r;
        r.x = r0.x + r1.x + r2.x + r3.x + ce * sf.x;
        r.y = r0.y + r1.y + r2.y + r3.y + ce * sf.y;
        r.z = r0.z + r1.z + r2.z + r3.z + ce * sf.z;
        r.w = r0.w + r1.w + r2.w + r3.w + ce * sf.w;
        ((float4*)g_z)[(size_t)n * 32 + lane] = r;
    }
}

// ---------------- tf32 mma.sync GEMM: Y[128-tile,128] = act(A) @ W ----------------
// A smem [128][132] row-major (row, k). B smem [128][132] as (n, k).
// 8 warps in 2x4; each warp: 64 rows x 32 cols = 4x4 m16n8k8 tiles.
#define SMEM_FLOATS (2 * 128 * 132)

template <bool IN_BN>
__global__ __launch_bounds__(256, 1) void gemm_mma(
    const float* __restrict__ A, const float* __restrict__ Bt,
    const float* __restrict__ scaleIn, const float* __restrict__ shiftIn,
    float* __restrict__ Y, int N)
{
    extern __shared__ float sm[];
    float* As = sm;                 // 128*132
    float* Bs = sm + 128 * 132;     // 128*132

    const int tid = threadIdx.x;
    const int wid = tid >> 5, lane = tid & 31;
    const int g = lane >> 2, t = lane & 3;       // groupID, threadID_in_group
    const int warprow = wid & 1;                 // 0..1 (64-row halves)
    const int warpcol = wid >> 1;                // 0..3 (32-col quarters)
    const int rowBase = blockIdx.x * 128;

    // B: copy pre-transposed tf32 weights (4096 float4)
    {
        const float4* Bi = (const float4*)Bt;
        #pragma unroll
        for (int i = 0; i < 16; ++i) {
            int idx = tid + i * 256;
            int n = idx >> 5, q = idx & 31;
            *(float4*)&Bs[n * 132 + q * 4] = Bi[idx];
        }
    }

    // A: load with BN+lrelu fusion + tf32 rounding
    {
        const float4* Ag4 = (const float4*)A;
        #pragma unroll
        for (int i = 0; i < 16; ++i) {
            int idx = tid + i * 256;
            int row = idx >> 5, q = idx & 31;
            int grow = rowBase + row;
            float4 a = make_float4(0.f, 0.f, 0.f, 0.f);
            if (grow < N) a = Ag4[(size_t)grow * 32 + q];
            if (IN_BN) {
                float4 sc = ((const float4*)scaleIn)[q];
                float4 sh = ((const float4*)shiftIn)[q];
                a.x = lrelu(sc.x * a.x + sh.x);
                a.y = lrelu(sc.y * a.y + sh.y);
                a.z = lrelu(sc.z * a.z + sh.z);
                a.w = lrelu(sc.w * a.w + sh.w);
            }
            a.x = __uint_as_float(to_tf32(a.x));
            a.y = __uint_as_float(to_tf32(a.y));
            a.z = __uint_as_float(to_tf32(a.z));
            a.w = __uint_as_float(to_tf32(a.w));
            *(float4*)&As[row * 132 + q * 4] = a;
        }
    }
    __syncthreads();

    float acc[4][4][4];
    #pragma unroll
    for (int m = 0; m < 4; ++m)
        #pragma unroll
        for (int n = 0; n < 4; ++n)
            #pragma unroll
            for (int j = 0; j < 4; ++j) acc[m][n][j] = 0.f;

    #pragma unroll
    for (int ks = 0; ks < 16; ++ks) {
        const int k0 = ks * 8;
        uint32_t af[4][4];
        #pragma unroll
        for (int m = 0; m < 4; ++m) {
            const float* p = &As[(warprow * 64 + m * 16 + g) * 132 + k0 + t];
            af[m][0] = __float_as_uint(p[0]);
            af[m][1] = __float_as_uint(p[8 * 132]);
            af[m][2] = __float_as_uint(p[4]);
            af[m][3] = __float_as_uint(p[8 * 132 + 4]);
        }
        #pragma unroll
        for (int n = 0; n < 4; ++n) {
            const float* p = &Bs[(warpcol * 32 + n * 8 + g) * 132 + k0 + t];
            uint32_t b0 = __float_as_uint(p[0]);
            uint32_t b1 = __float_as_uint(p[4]);
            #pragma unroll
            for (int m = 0; m < 4; ++m) {
                asm volatile(
                    "mma.sync.aligned.m16n8k8.row.col.f32.tf32.tf32.f32 "
                    "{%0,%1,%2,%3}, {%4,%5,%6,%7}, {%8,%9}, {%0,%1,%2,%3};"
                    : "+f"(acc[m][n][0]), "+f"(acc[m][n][1]),
                      "+f"(acc[m][n][2]), "+f"(acc[m][n][3])
                    : "r"(af[m][0]), "r"(af[m][1]), "r"(af[m][2]), "r"(af[m][3]),
                      "r"(b0), "r"(b1));
            }
        }
    }

    // epilogue: direct float2 stores
    #pragma unroll
    for (int m = 0; m < 4; ++m) {
        int r = rowBase + warprow * 64 + m * 16 + g;
        #pragma unroll
        for (int n = 0; n < 4; ++n) {
            int c = warpcol * 32 + n * 8 + 2 * t;
            if (r < N)
                *(float2*)&Y[(size_t)r * 128 + c] = make_float2(acc[m][n][0], acc[m][n][1]);
            if (r + 8 < N)
                *(float2*)&Y[(size_t)(r + 8) * 128 + c] = make_float2(acc[m][n][2], acc[m][n][3]);
        }
    }
}

// ---------------- column stats over Y ----------------
__global__ __launch_bounds__(256) void stats_kernel(const float* __restrict__ Y,
                                                    float* __restrict__ sum, float* __restrict__ sqs, int N)
{
    __shared__ float red[8 * 128];
    int tid = threadIdx.x;
    int q = tid & 31, rset = tid >> 5;
    int rowsPer = (N + gridDim.x - 1) / gridDim.x;
    int r0 = blockIdx.x * rowsPer;
    int r1 = min(N, r0 + rowsPer);
    const float4* Y4 = (const float4*)Y;

    float4 s = make_float4(0.f, 0.f, 0.f, 0.f);
    float4 ss = make_float4(0.f, 0.f, 0.f, 0.f);
    for (int r = r0 + rset; r < r1; r += 8) {
        float4 y = Y4[(size_t)r * 32 + q];
        s.x += y.x; s.y += y.y; s.z += y.z; s.w += y.w;
        ss.x += y.x * y.x; ss.y += y.y * y.y; ss.z += y.z * y.z; ss.w += y.w * y.w;
    }
    *(float4*)&red[rset * 128 + q * 4] = s;
    __syncthreads();
    if (tid < 128) {
        float tt = 0.f;
        #pragma unroll
        for (int r = 0; r < 8; ++r) tt += red[r * 128 + tid];
        atomicAdd(&sum[tid], tt);
    }
    __syncthreads();
    *(float4*)&red[rset * 128 + q * 4] = ss;
    __syncthreads();
    if (tid < 128) {
        float tt = 0.f;
        #pragma unroll
        for (int r = 0; r < 8; ++r) tt += red[r * 128 + tid];
        atomicAdd(&sqs[tid], tt);
    }
}

// ---------------- BN finalize ----------------
__global__ void bn_fin_kernel(const float* __restrict__ sum, const float* __restrict__ sqs,
                              const float* __restrict__ g, const float* __restrict__ be,
                              float* __restrict__ scale, float* __restrict__ shift, float invN)
{
    int c = threadIdx.x;
    float m = sum[c] * invN;
    float var = sqs[c] * invN - m * m;
    float s = g[c] * rsqrtf(var + BN_EPS);
    scale[c] = s;
    shift[c] = be[c] - m * s;
}

// ---------------- final BN + leaky_relu apply ----------------
__global__ void apply_kernel(const float* __restrict__ Y,
                             const float* __restrict__ scale, const float* __restrict__ shift,
                             float* __restrict__ out, int N)
{
    size_t i = (size_t)blockIdx.x * blockDim.x + threadIdx.x;
    if (i < (size_t)N * 32) {
        int c = (int)(i & 31);
        float4 sc = ((const float4*)scale)[c];
        float4 sh = ((const float4*)shift)[c];
        float4 y = ((const float4*)Y)[i];
        float4 o;
        o.x = lrelu(sc.x * y.x + sh.x);
        o.y = lrelu(sc.y * y.y + sh.y);
        o.z = lrelu(sc.z * y.z + sh.z);
        o.w = lrelu(sc.w * y.w + sh.w);
        ((float4*)out)[i] = o;
    }
}

// ---------------- launch ----------------
extern "C" void kernel_launch(void* const* d_in, const int* in_sizes, int n_in,
                              void* d_out, int out_size) {
    const float* self  = (const float*)d_in[0];
    const float* neigh = (const float*)d_in[1];
    const float* W_t   = (const float*)d_in[2];
    const float* a_att = (const float*)d_in[3];
    const float* epsp  = (const float*)d_in[4];
    const float* W1 = (const float*)d_in[5];
    const float* g1 = (const float*)d_in[7];
    const float* be1 = (const float*)d_in[8];
    const float* W2 = (const float*)d_in[9];
    const float* g2 = (const float*)d_in[11];
    const float* be2 = (const float*)d_in[12];
    const float* W3 = (const float*)d_in[13];
    const float* g3 = (const float*)d_in[15];
    const float* be3 = (const float*)d_in[16];

    int N = in_sizes[0] / 128;
    int K = (int)((long long)in_sizes[1] / ((long long)N * 128));

    float *z, *bufA, *bufB, *Wc, *Bt, *sum, *sqs, *scale, *shift;
    cudaGetSymbolAddress((void**)&z,     g_z);
    cudaGetSymbolAddress((void**)&bufA,  g_bufA);
    cudaGetSymbolAddress((void**)&bufB,  g_bufB);
    cudaGetSymbolAddress((void**)&Wc,    g_Wc);
    cudaGetSymbolAddress((void**)&Bt,    g_Bt);
    cudaGetSymbolAddress((void**)&sum,   g_sum);
    cudaGetSymbolAddress((void**)&sqs,   g_sqs);
    cudaGetSymbolAddress((void**)&scale, g_scale);
    cudaGetSymbolAddress((void**)&shift, g_shift);

    size_t smemBytes = (size_t)SMEM_FLOATS * sizeof(float);  // 135168
    cudaFuncSetAttribute(gemm_mma<false>, cudaFuncAttributeMaxDynamicSharedMemorySize, (int)smemBytes);
    cudaFuncSetAttribute(gemm_mma<true>,  cudaFuncAttributeMaxDynamicSharedMemorySize, (int)smemBytes);

    float invN = 1.f / (float)N;
    int gemmGrid = (N + 127) / 128;

    prep_kernel<<<1, 128>>>(W_t, a_att);
    wc_kernel<<<16, 128>>>(W_t, W1);
    buildB_kernel<<<64, 256>>>(Wc, Bt);             // layer 0: W_t@W1
    buildB_kernel<<<64, 256>>>(W2, Bt + 16384);     // layer 1
    buildB_kernel<<<64, 256>>>(W3, Bt + 32768);     // layer 2

    attn_kernel<<<N, 128>>>(self, neigh, epsp, N, K);

    // y1 = z @ Wc  (bias no-op under BN)
    gemm_mma<false><<<gemmGrid, 256, smemBytes>>>(z, Bt, nullptr, nullptr, bufA, N);
    stats_kernel<<<256, 256>>>(bufA, sum, sqs, N);
    bn_fin_kernel<<<1, 128>>>(sum, sqs, g1, be1, scale, shift, invN);

    // y2 = act1(y1) @ W2
    gemm_mma<true><<<gemmGrid, 256, smemBytes>>>(bufA, Bt + 16384, scale, shift, bufB, N);
    stats_kernel<<<256, 256>>>(bufB, sum + 128, sqs + 128, N);
    bn_fin_kernel<<<1, 128>>>(sum + 128, sqs + 128, g2, be2, scale + 128, shift + 128, invN);

    // y3 = act2(y2) @ W3
    gemm_mma<true><<<gemmGrid, 256, smemBytes>>>(bufB, Bt + 32768, scale + 128, shift + 128, bufA, N);
    stats_kernel<<<256, 256>>>(bufA, sum + 256, sqs + 256, N);
    bn_fin_kernel<<<1, 128>>>(sum + 256, sqs + 256, g3, be3, scale + 256, shift + 256, invN);

    // out = act3(y3)
    int applyGrid = (int)(((size_t)N * 32 + 255) / 256);
    apply_kernel<<<applyGrid, 256>>>(bufA, scale + 256, shift + 256, (float*)d_out, N);
}